// round 1
// baseline (speedup 1.0000x reference)
#include <cuda_runtime.h>
#include <math.h>

#define HH 512
#define WW 512
#define HW (512*512)
#define NB 8
#define NC 3
#define NPIX (NB*NC*HW)
#define PI_F 3.14159265358979f

// ---------------- scratch (device globals; no allocations) ----------------
__device__ float2 g_U[NB*NC*HW];        // 50 MB  complex field
__device__ float  g_Hb[NB*32*HW];       // 256 MB hidden (ph|z), reused as y1
__device__ float  g_Y2[NB*32*HW];       // 256 MB mix conv2 raw out
__device__ float  g_J[NB*NC*HW];        // 25 MB
__device__ float  g_delta[NB*NC*HW];    // 25 MB
__device__ float2 g_twid[256];
__device__ double g_zsum[NB*NC];
__device__ float  g_xmu[NB], g_xrs[NB];
__device__ double g_s1y1[NB], g_s2y1[NB], g_s1y2[NB], g_s2y2[NB];
__device__ double g_psum[NB*NC];
__device__ float  g_wse[NB*NC];

__device__ __forceinline__ int rev9(int x){ return (int)(__brev((unsigned)x) >> 23); }
__device__ __forceinline__ float siluf(float v){ return v / (1.f + __expf(-v)); }
__device__ __forceinline__ float warpSum(float v){
    #pragma unroll
    for (int o=16;o;o>>=1) v += __shfl_down_sync(0xffffffffu, v, o);
    return v;
}

// ---------------- init: twiddles + zero accumulators ----------------
__global__ void k_init(){
    int t = threadIdx.x;
    if (t < 256){
        double ang = -2.0*3.14159265358979323846*(double)t/512.0;
        g_twid[t] = make_float2((float)cos(ang), (float)sin(ang));
    }
    if (t < NB*NC){ g_zsum[t]=0.0; g_psum[t]=0.0; }
    if (t < NB){ g_s1y1[t]=0.0; g_s2y1[t]=0.0; g_s1y2[t]=0.0; g_s2y2[t]=0.0; }
}

// ---------------- x groupnorm stats (per batch) ----------------
__global__ void k_xstats(const float* __restrict__ x){
    int b = blockIdx.x, t = threadIdx.x;
    const float* p = x + (size_t)b*NC*HW;
    float s=0.f, ss=0.f;
    for (int i=t;i<NC*HW;i+=256){ float v=p[i]; s+=v; ss+=v*v; }
    __shared__ float r1[256], r2[256];
    r1[t]=s; r2[t]=ss; __syncthreads();
    for (int o=128;o;o>>=1){ if(t<o){ r1[t]+=r1[t+o]; r2[t]+=r2[t+o]; } __syncthreads(); }
    if (t==0){
        float N = (float)(NC*HW);
        float mu = r1[0]/N;
        float var = r2[0]/N - mu*mu;
        g_xmu[b] = mu;
        g_xrs[b] = rsqrtf(var + 1e-5f);
    }
}

// ---------------- fused ph1 + z1 conv: xn(3) -> 32ch, silu ----------------
__global__ void k_conv1(const float* __restrict__ x,
                        const float* __restrict__ ng, const float* __restrict__ nbv,
                        const float* __restrict__ pw1, const float* __restrict__ pb1,
                        const float* __restrict__ zw1, const float* __restrict__ zb1){
    __shared__ float s_in[3*324];
    __shared__ float s_w[27*32];
    __shared__ float s_b[32];
    __shared__ float s_sc[3], s_sh[3];
    int b = blockIdx.z;
    int t = threadIdx.x, tx = t&15, ty = t>>4;
    int oy0 = blockIdx.y*16, ox0 = blockIdx.x*16;
    if (t < 3){
        float rs = g_xrs[b], mu = g_xmu[b];
        s_sc[t] = ng[t]*rs;
        s_sh[t] = nbv[t] - mu*rs*ng[t];
    }
    for (int g=t; g<864; g+=256){
        int co=g/27, r=g%27;
        float w = (co<16) ? pw1[g] : zw1[(co-16)*27+r];
        s_w[r*32+co] = w;
    }
    if (t<32) s_b[t] = (t<16) ? pb1[t] : zb1[t-16];
    __syncthreads();
    for (int g=t; g<3*324; g+=256){
        int ci=g/324, r=g%324, iy=r/18, ix=r%18;
        int gy=oy0+iy-1, gx=ox0+ix-1;
        float v = 0.f;
        if (gy>=0 && gy<HH && gx>=0 && gx<WW)
            v = x[(size_t)(b*3+ci)*HW + gy*WW + gx]*s_sc[ci] + s_sh[ci];
        s_in[g] = v;
    }
    __syncthreads();
    float acc[32];
    #pragma unroll
    for (int co=0;co<32;co++) acc[co]=s_b[co];
    #pragma unroll
    for (int ci=0;ci<3;ci++)
    #pragma unroll
    for (int ky=0;ky<3;ky++)
    #pragma unroll
    for (int kx=0;kx<3;kx++){
        float v = s_in[ci*324 + (ty+ky)*18 + (tx+kx)];
        const float* wr = &s_w[(ci*9+ky*3+kx)*32];
        #pragma unroll
        for (int co=0;co<32;co++) acc[co] += wr[co]*v;
    }
    int gy=oy0+ty, gx=ox0+tx;
    size_t base = (size_t)b*32*HW + gy*WW + gx;
    #pragma unroll
    for (int co=0;co<32;co++) g_Hb[base + (size_t)co*HW] = siluf(acc[co]);
}

// -------- ph2 (phi->U0) + z2 (-> z mean) from 32ch hidden --------
__global__ void k_headout(const float* __restrict__ x,
                          const float* __restrict__ pw2, const float* __restrict__ pb2,
                          const float* __restrict__ zw2, const float* __restrict__ zb2){
    __shared__ float s_h[32*324];      // 41.5 KB
    __shared__ float s_wp[144*3], s_wz[144*3];
    __shared__ float s_bp[3], s_bz[3];
    __shared__ float s_red[256];
    int b = blockIdx.z;
    int t = threadIdx.x, tx=t&15, ty=t>>4;
    int oy0 = blockIdx.y*16, ox0 = blockIdx.x*16;
    for (int g=t; g<432; g+=256){
        int co=g/144, r=g%144;
        s_wp[r*3+co] = pw2[g];
        s_wz[r*3+co] = zw2[g];
    }
    if (t<3){ s_bp[t]=pb2[t]; s_bz[t]=zb2[t]; }
    for (int g=t; g<32*324; g+=256){
        int ci=g/324, r=g%324, iy=r/18, ix=r%18;
        int gy=oy0+iy-1, gx=ox0+ix-1;
        float v=0.f;
        if (gy>=0 && gy<HH && gx>=0 && gx<WW)
            v = g_Hb[(size_t)(b*32+ci)*HW + gy*WW + gx];
        s_h[g]=v;
    }
    __syncthreads();
    float ap[3] = {s_bp[0], s_bp[1], s_bp[2]};
    float az[3] = {s_bz[0], s_bz[1], s_bz[2]};
    #pragma unroll
    for (int ci=0;ci<16;ci++)
    #pragma unroll
    for (int ky=0;ky<3;ky++)
    #pragma unroll
    for (int kx=0;kx<3;kx++){
        int off = (ty+ky)*18 + tx+kx;
        float vp = s_h[ci*324 + off];
        float vz = s_h[(16+ci)*324 + off];
        int r = ci*9+ky*3+kx;
        #pragma unroll
        for (int co=0;co<3;co++){
            ap[co] += s_wp[r*3+co]*vp;
            az[co] += s_wz[r*3+co]*vz;
        }
    }
    int gy=oy0+ty, gx=ox0+tx;
    float zl[3];
    #pragma unroll
    for (int co=0;co<3;co++){
        float phi = tanhf(ap[co]) * PI_F;
        size_t p = (size_t)(b*3+co)*HW + gy*WW + gx;
        float xv = x[p];
        float sn, cs; __sincosf(phi, &sn, &cs);
        g_U[p] = make_float2(xv*cs, xv*sn);
        zl[co] = 0.3f / (1.f + __expf(-az[co]));
    }
    #pragma unroll
    for (int co=0;co<3;co++){
        __syncthreads();
        s_red[t] = zl[co]; __syncthreads();
        for (int o=128;o;o>>=1){ if (t<o) s_red[t]+=s_red[t+o]; __syncthreads(); }
        if (t==0) atomicAdd(&g_zsum[b*3+co], (double)s_red[0]);
    }
}

// ---------------- 512-pt FFT core (AoS, rows) ----------------
__device__ __forceinline__ void fft512(float2* s, const float2* tw, int t, bool inv){
    #pragma unroll
    for (int st=1; st<=9; st++){
        int half = 1<<(st-1);
        int grp = t >> (st-1);
        int j   = t & (half-1);
        int i   = (grp << st) + j;
        float2 w = tw[j << (9-st)];
        float wy = inv ? -w.y : w.y;
        float2 u = s[i], v = s[i+half];
        float vr = v.x*w.x - v.y*wy;
        float vi = v.x*wy + v.y*w.x;
        s[i]      = make_float2(u.x+vr, u.y+vi);
        s[i+half] = make_float2(u.x-vr, u.y-vi);
        __syncthreads();
    }
}

__global__ void k_fftrow_fwd(){
    __shared__ float2 s[512];
    __shared__ float2 tw[256];
    int t = threadIdx.x;
    size_t base = (size_t)blockIdx.x * 512;
    tw[t] = g_twid[t];
    float2 a = g_U[base+t], b = g_U[base+t+256];
    s[rev9(t)] = a; s[rev9(t+256)] = b;
    __syncthreads();
    fft512(s, tw, t, false);
    g_U[base+t] = s[t]; g_U[base+t+256] = s[t+256];
}

__global__ void k_ifftrow_mag(){
    __shared__ float2 s[512];
    __shared__ float2 tw[256];
    int t = threadIdx.x;
    size_t base = (size_t)blockIdx.x * 512;
    tw[t] = g_twid[t];
    float2 a = g_U[base+t], b = g_U[base+t+256];
    s[rev9(t)] = a; s[rev9(t+256)] = b;
    __syncthreads();
    fft512(s, tw, t, true);
    const float sc = 1.f/262144.f;
    #pragma unroll
    for (int e2=0;e2<2;e2++){
        int e = t + e2*256;
        float re = s[e].x*sc, im = s[e].y*sc;
        g_J[base+e] = sqrtf(fmaxf(re*re+im*im, 1e-12f));
    }
}

// ------- col FFT fwd + freq filter + col IFFT (8 cols/block, SoA pad 9) -------
__global__ void k_fftcol(const float* __restrict__ freq_gain){
    __shared__ float sRe[4608], sIm[4608];
    __shared__ float2 tw[256];
    int bid = blockIdx.x;
    int bc = bid>>6, cb = bid&63;
    int c = bc%3;
    int t = threadIdx.x;
    int cc = t&7, lr = t>>3;
    int col = cb*8 + cc;
    size_t base = (size_t)bc*HW;
    tw[t] = g_twid[t];
    #pragma unroll
    for (int k=0;k<16;k++){
        int r = lr + 32*k;
        float2 v = g_U[base + (size_t)r*WW + col];
        int rr = rev9(r);
        sRe[rr*9+cc] = v.x; sIm[rr*9+cc] = v.y;
    }
    __syncthreads();
    // forward stages
    #pragma unroll
    for (int st=1; st<=9; st++){
        int half = 1<<(st-1);
        #pragma unroll
        for (int k=0;k<8;k++){
            int bf = lr + 32*k;
            int grp = bf >> (st-1), j = bf & (half-1);
            int i = (grp<<st) + j;
            float2 w = tw[j << (9-st)];
            int e0 = i*9+cc, e1 = (i+half)*9+cc;
            float ur=sRe[e0], ui=sIm[e0], vr0=sRe[e1], vi0=sIm[e1];
            float vr = vr0*w.x - vi0*w.y;
            float vi = vr0*w.y + vi0*w.x;
            sRe[e0]=ur+vr; sIm[e0]=ui+vi;
            sRe[e1]=ur-vr; sIm[e1]=ui-vi;
        }
        __syncthreads();
    }
    // filter: (1+freq_gain[c]) * exp(i * kz * z_mean)
    const float lam2inv = (c==0) ? (1.f/(0.65f*0.65f)) : (c==1) ? (1.f/(0.53f*0.53f)) : (1.f/(0.47f*0.47f));
    float zm = (float)(g_zsum[bc] * (1.0/262144.0));
    float gain = 1.f + freq_gain[c];
    float fx = (float)((col<256)?col:col-512) * (1.f/512.f);
    float fx2 = fx*fx;
    #pragma unroll
    for (int k=0;k<16;k++){
        int r = lr + 32*k;
        float fy = (float)((r<256)?r:r-512) * (1.f/512.f);
        float f2 = fy*fy + fx2;
        float kz = 6.28318530717958f * sqrtf(fmaxf(lam2inv - f2, 0.f));
        float hp = kz*zm;
        float sn, cs; __sincosf(hp, &sn, &cs);
        int e = r*9+cc;
        float re=sRe[e], im=sIm[e];
        sRe[e] = gain*(re*cs - im*sn);
        sIm[e] = gain*(re*sn + im*cs);
    }
    __syncthreads();
    // bit-reverse permutation for inverse pass
    #pragma unroll
    for (int k=0;k<16;k++){
        int r = lr + 32*k;
        int r2 = rev9(r);
        if (r < r2){
            int e=r*9+cc, e2=r2*9+cc;
            float a=sRe[e]; sRe[e]=sRe[e2]; sRe[e2]=a;
            float bb=sIm[e]; sIm[e]=sIm[e2]; sIm[e2]=bb;
        }
    }
    __syncthreads();
    // inverse stages (conjugate twiddles)
    #pragma unroll
    for (int st=1; st<=9; st++){
        int half = 1<<(st-1);
        #pragma unroll
        for (int k=0;k<8;k++){
            int bf = lr + 32*k;
            int grp = bf >> (st-1), j = bf & (half-1);
            int i = (grp<<st) + j;
            float2 w = tw[j << (9-st)];
            float wy = -w.y;
            int e0 = i*9+cc, e1 = (i+half)*9+cc;
            float ur=sRe[e0], ui=sIm[e0], vr0=sRe[e1], vi0=sIm[e1];
            float vr = vr0*w.x - vi0*wy;
            float vi = vr0*wy + vi0*w.x;
            sRe[e0]=ur+vr; sIm[e0]=ui+vi;
            sRe[e1]=ur-vr; sIm[e1]=ui-vi;
        }
        __syncthreads();
    }
    #pragma unroll
    for (int k=0;k<16;k++){
        int r = lr + 32*k;
        g_U[base + (size_t)r*WW + col] = make_float2(sRe[r*9+cc], sIm[r*9+cc]);
    }
}

// ---------------- mix conv1: [x, J_l, J_l-x_l](5) -> 32, raw + stats ----------------
__global__ void k_mixconv1(const float* __restrict__ x,
                           const float* __restrict__ w1, const float* __restrict__ b1){
    __shared__ float s_in[5*324];
    __shared__ float s_w[45*32];
    __shared__ float s_b[32];
    __shared__ float s_r1[8], s_r2[8];
    int b = blockIdx.z;
    int t = threadIdx.x, tx=t&15, ty=t>>4;
    int oy0 = blockIdx.y*16, ox0 = blockIdx.x*16;
    for (int g=t; g<1440; g+=256){ int co=g/45, r=g%45; s_w[r*32+co]=w1[g]; }
    if (t<32) s_b[t]=b1[t];
    for (int g=t; g<324; g+=256){
        int iy=g/18, ix=g%18;
        int gy=oy0+iy-1, gx=ox0+ix-1;
        float x0=0,x1=0,x2=0,j0=0,j1=0,j2=0;
        if (gy>=0 && gy<HH && gx>=0 && gx<WW){
            size_t p = (size_t)b*3*HW + gy*WW + gx;
            x0=x[p]; x1=x[p+HW]; x2=x[p+2*HW];
            j0=g_J[p]; j1=g_J[p+HW]; j2=g_J[p+2*HW];
        }
        float xl = 0.299f*x0 + 0.587f*x1 + 0.114f*x2;
        float jl = 0.299f*j0 + 0.587f*j1 + 0.114f*j2;
        s_in[g]       = x0;
        s_in[324+g]   = x1;
        s_in[648+g]   = x2;
        s_in[972+g]   = jl;
        s_in[1296+g]  = jl - xl;
    }
    __syncthreads();
    float acc[32];
    #pragma unroll
    for (int co=0;co<32;co++) acc[co]=s_b[co];
    #pragma unroll
    for (int ci=0;ci<5;ci++)
    #pragma unroll
    for (int ky=0;ky<3;ky++)
    #pragma unroll
    for (int kx=0;kx<3;kx++){
        float v = s_in[ci*324 + (ty+ky)*18 + (tx+kx)];
        const float* wr = &s_w[(ci*9+ky*3+kx)*32];
        #pragma unroll
        for (int co=0;co<32;co++) acc[co] += wr[co]*v;
    }
    int gy=oy0+ty, gx=ox0+tx;
    size_t base = (size_t)b*32*HW + gy*WW + gx;
    float ls=0.f, lss=0.f;
    #pragma unroll
    for (int co=0;co<32;co++){
        float v = acc[co];
        g_Hb[base + (size_t)co*HW] = v;
        ls += v; lss += v*v;
    }
    float w1s = warpSum(ls), w2s = warpSum(lss);
    int lane=t&31, wid=t>>5;
    if (lane==0){ s_r1[wid]=w1s; s_r2[wid]=w2s; }
    __syncthreads();
    if (t==0){
        float a=0.f, bb=0.f;
        #pragma unroll
        for (int i=0;i<8;i++){ a+=s_r1[i]; bb+=s_r2[i]; }
        atomicAdd(&g_s1y1[b], (double)a);
        atomicAdd(&g_s2y1[b], (double)bb);
    }
}

// ---------------- mix conv2: silu(gn(y1))(32) -> 32, raw + stats ----------------
__global__ void k_mixconv2(const float* __restrict__ w2, const float* __restrict__ b2,
                           const float* __restrict__ g1g, const float* __restrict__ g1b){
    extern __shared__ float sm[];
    float* s_in = sm;              // 10368
    float* s_w  = sm + 10368;      // 9216
    float* s_b  = s_w + 9216;      // 32
    float* s_A  = s_b + 32;        // 32
    float* s_B  = s_A + 32;        // 32
    __shared__ float s_r1[8], s_r2[8];
    int b = blockIdx.z;
    int t = threadIdx.x, tx=t&15, ty=t>>4;
    int oy0 = blockIdx.y*16, ox0 = blockIdx.x*16;
    if (t<32){
        double N = 8388608.0;
        double mu = g_s1y1[b]/N;
        double var = g_s2y1[b]/N - mu*mu;
        float rs = rsqrtf((float)var + 1e-5f);
        float A = rs*g1g[t];
        s_A[t]=A; s_B[t]=g1b[t]-(float)mu*A;
        s_b[t]=b2[t];
    }
    for (int g=t; g<9216; g+=256){ int co=g/288, r=g%288; s_w[r*32+co]=w2[g]; }
    __syncthreads();
    for (int g=t; g<32*324; g+=256){
        int ci=g/324, r=g%324, iy=r/18, ix=r%18;
        int gy=oy0+iy-1, gx=ox0+ix-1;
        float v=0.f;
        if (gy>=0 && gy<HH && gx>=0 && gx<WW){
            float y = g_Hb[(size_t)(b*32+ci)*HW + gy*WW + gx];
            float yn = y*s_A[ci] + s_B[ci];
            v = siluf(yn);
        }
        s_in[g]=v;
    }
    __syncthreads();
    float acc[32];
    #pragma unroll
    for (int co=0;co<32;co++) acc[co]=s_b[co];
    #pragma unroll
    for (int ci=0;ci<32;ci++)
    #pragma unroll
    for (int ky=0;ky<3;ky++)
    #pragma unroll
    for (int kx=0;kx<3;kx++){
        float v = s_in[ci*324 + (ty+ky)*18 + (tx+kx)];
        const float* wr = &s_w[(ci*9+ky*3+kx)*32];
        #pragma unroll
        for (int co=0;co<32;co++) acc[co] += wr[co]*v;
    }
    int gy=oy0+ty, gx=ox0+tx;
    size_t base = (size_t)b*32*HW + gy*WW + gx;
    float ls=0.f, lss=0.f;
    #pragma unroll
    for (int co=0;co<32;co++){
        float v = acc[co];
        g_Y2[base + (size_t)co*HW] = v;
        ls += v; lss += v*v;
    }
    float w1s = warpSum(ls), w2s = warpSum(lss);
    int lane=t&31, wid=t>>5;
    if (lane==0){ s_r1[wid]=w1s; s_r2[wid]=w2s; }
    __syncthreads();
    if (t==0){
        float a=0.f, bb=0.f;
        #pragma unroll
        for (int i=0;i<8;i++){ a+=s_r1[i]; bb+=s_r2[i]; }
        atomicAdd(&g_s1y2[b], (double)a);
        atomicAdd(&g_s2y2[b], (double)bb);
    }
}

// ---------------- mix conv3 (1x1) -> delta + per-channel mean ----------------
__global__ void k_mixconv3(const float* __restrict__ w3, const float* __restrict__ b3,
                           const float* __restrict__ g2g, const float* __restrict__ g2b){
    __shared__ float s_w[96], s_b3[3], s_A[32], s_B[32];
    __shared__ float s_r[8];
    int b = blockIdx.y;
    int t = threadIdx.x;
    int pix = blockIdx.x*256 + t;
    if (t<32){
        double N = 8388608.0;
        double mu = g_s1y2[b]/N;
        double var = g_s2y2[b]/N - mu*mu;
        float rs = rsqrtf((float)var + 1e-5f);
        float A = rs*g2g[t];
        s_A[t]=A; s_B[t]=g2b[t]-(float)mu*A;
    }
    if (t<96) s_w[t]=w3[t];
    if (t<3)  s_b3[t]=b3[t];
    __syncthreads();
    float a0=s_b3[0], a1=s_b3[1], a2=s_b3[2];
    size_t base = (size_t)b*32*HW + pix;
    #pragma unroll
    for (int ci=0;ci<32;ci++){
        float y = g_Y2[base + (size_t)ci*HW];
        float yn = y*s_A[ci] + s_B[ci];
        float v = siluf(yn);
        a0 += s_w[ci]*v; a1 += s_w[32+ci]*v; a2 += s_w[64+ci]*v;
    }
    size_t dbase = (size_t)b*3*HW + pix;
    g_delta[dbase]      = a0;
    g_delta[dbase+HW]   = a1;
    g_delta[dbase+2*HW] = a2;
    float av[3] = {a0, a1, a2};
    int lane=t&31, wid=t>>5;
    #pragma unroll
    for (int co=0;co<3;co++){
        float ws = warpSum(av[co]);
        if (lane==0) s_r[wid]=ws;
        __syncthreads();
        if (t==0){
            float s=0.f;
            #pragma unroll
            for (int i=0;i<8;i++) s+=s_r[i];
            atomicAdd(&g_psum[b*3+co], (double)s);
        }
        __syncthreads();
    }
}

// ---------------- SE gate ----------------
__global__ void k_se(const float* __restrict__ w1, const float* __restrict__ b1,
                     const float* __restrict__ w2, const float* __restrict__ b2){
    int t = threadIdx.x;
    if (t < NB){
        float p[3];
        #pragma unroll
        for (int c=0;c<3;c++) p[c] = (float)(g_psum[t*3+c] * (1.0/262144.0));
        float h[4];
        #pragma unroll
        for (int j=0;j<4;j++){
            float a = b1[j];
            #pragma unroll
            for (int c=0;c<3;c++) a += w1[j*3+c]*p[c];
            h[j] = a/(1.f+__expf(-a));
        }
        #pragma unroll
        for (int c=0;c<3;c++){
            float a = b2[c];
            #pragma unroll
            for (int j=0;j<4;j++) a += w2[c*4+j]*h[j];
            g_wse[t*3+c] = 1.f/(1.f+__expf(-a));
        }
    }
}

// ---------------- final: out = x + alpha * delta * wse ----------------
__global__ void k_final(const float* __restrict__ x, const float* __restrict__ alpha,
                        float* __restrict__ out){
    int i = blockIdx.x*256 + threadIdx.x;
    if (i >= NPIX) return;
    int bc = i / HW;
    out[i] = x[i] + alpha[0]*g_delta[i]*g_wse[bc];
}

// ---------------- launch ----------------
extern "C" void kernel_launch(void* const* d_in, const int* in_sizes, int n_in,
                              void* d_out, int out_size){
    const float* x    = (const float*)d_in[0];
    const float* ng   = (const float*)d_in[1];
    const float* nbv  = (const float*)d_in[2];
    const float* pw1  = (const float*)d_in[3];
    const float* pb1  = (const float*)d_in[4];
    const float* pw2  = (const float*)d_in[5];
    const float* pb2  = (const float*)d_in[6];
    const float* zw1  = (const float*)d_in[7];
    const float* zb1  = (const float*)d_in[8];
    const float* zw2  = (const float*)d_in[9];
    const float* zb2  = (const float*)d_in[10];
    const float* fg   = (const float*)d_in[11];
    const float* mw1  = (const float*)d_in[12];
    const float* mb1  = (const float*)d_in[13];
    const float* g1g  = (const float*)d_in[14];
    const float* g1b  = (const float*)d_in[15];
    const float* mw2  = (const float*)d_in[16];
    const float* mb2  = (const float*)d_in[17];
    const float* g2g  = (const float*)d_in[18];
    const float* g2b  = (const float*)d_in[19];
    const float* mw3  = (const float*)d_in[20];
    const float* mb3  = (const float*)d_in[21];
    const float* sw1  = (const float*)d_in[22];
    const float* sb1  = (const float*)d_in[23];
    const float* sw2  = (const float*)d_in[24];
    const float* sb2  = (const float*)d_in[25];
    const float* alpha= (const float*)d_in[26];

    const int SMEM_I = (10368 + 9216 + 32 + 32 + 32) * 4; // 78720 B
    cudaFuncSetAttribute(k_mixconv2, cudaFuncAttributeMaxDynamicSharedMemorySize, SMEM_I);

    dim3 g16(32, 32, NB);
    k_init<<<1,256>>>();
    k_xstats<<<NB,256>>>(x);
    k_conv1<<<g16,256>>>(x, ng, nbv, pw1, pb1, zw1, zb1);
    k_headout<<<g16,256>>>(x, pw2, pb2, zw2, zb2);
    k_fftrow_fwd<<<NB*NC*512,256>>>();
    k_fftcol<<<NB*NC*64,256>>>(fg);
    k_ifftrow_mag<<<NB*NC*512,256>>>();
    k_mixconv1<<<g16,256>>>(x, mw1, mb1);
    k_mixconv2<<<g16,256,SMEM_I>>>(mw2, mb2, g1g, g1b);
    k_mixconv3<<<dim3(HW/256, NB),256>>>(mw3, mb3, g2g, g2b);
    k_se<<<1,32>>>(sw1, sb1, sw2, sb2);
    k_final<<<NPIX/256,256>>>(x, alpha, (float*)d_out);
}